// round 4
// baseline (speedup 1.0000x reference)
#include <cuda_runtime.h>
#include <cstdint>

typedef unsigned long long ull;
#define FULLMASK 0xFFFFFFFFu

// Scratch for combined features [vx,vy,vz, rx,ry,rz] per row (64*1024 rows).
__device__ float g_comb[64 * 1024 * 6];

// ---------------------------------------------------------------------------
// Kernel 1: top-4 smallest distances per row -> combined features
// One warp per row. Keys are ((u32)float_bits << 32) | index, so a single
// u64 '<' gives exact (value asc, index asc) ordering == JAX top_k ties.
// ---------------------------------------------------------------------------

__device__ __forceinline__ void cswap_u64(ull &a, ull &b) {
    if (b < a) { ull t = a; a = b; b = t; }
}

__device__ __forceinline__ void ins4(ull k, ull &k0, ull &k1, ull &k2, ull &k3) {
    if (k < k3) {
        k3 = k;
        cswap_u64(k2, k3);
        cswap_u64(k1, k2);
        cswap_u64(k0, k1);
    }
}

__global__ void __launch_bounds__(256) topk_kernel(const float* __restrict__ dm,
                                                   const float* __restrict__ vel) {
    const int warp = threadIdx.x >> 5;
    const int lane = threadIdx.x & 31;
    const int row  = blockIdx.x * 8 + warp;   // < 65536
    const float* drow = dm + (size_t)row * 1024;

    ull k0 = ~0ull, k1 = ~0ull, k2 = ~0ull, k3 = ~0ull;

    #pragma unroll 4
    for (int j = lane; j < 1024; j += 32) {
        float d = drow[j];
        ull key = ((ull)__float_as_uint(d) << 32) | (unsigned)j;
        ins4(key, k0, k1, k2, k3);
    }

    // Warp butterfly merge of per-lane sorted top-4 lists.
    #pragma unroll
    for (int off = 16; off; off >>= 1) {
        ull m0 = __shfl_xor_sync(FULLMASK, k0, off);
        ull m1 = __shfl_xor_sync(FULLMASK, k1, off);
        ull m2 = __shfl_xor_sync(FULLMASK, k2, off);
        ull m3 = __shfl_xor_sync(FULLMASK, k3, off);
        ins4(m0, k0, k1, k2, k3);
        ins4(m1, k0, k1, k2, k3);
        ins4(m2, k0, k1, k2, k3);
        ins4(m3, k0, k1, k2, k3);
    }

    if (lane == 0) {
        const int b = row >> 10;
        const int a = row & 1023;
        const float* vb = vel + (size_t)b * (1024 * 3);
        // ranks 1,2,3 (rank 0 dropped per idx[...,1:])
        const int i1 = (int)(unsigned)k1;
        const int i2 = (int)(unsigned)k2;
        const int i3 = (int)(unsigned)k3;
        float sx = vb[a * 3 + 0], sy = vb[a * 3 + 1], sz = vb[a * 3 + 2];
        float nx = vb[i1 * 3 + 0] + vb[i2 * 3 + 0] + vb[i3 * 3 + 0];
        float ny = vb[i1 * 3 + 1] + vb[i2 * 3 + 1] + vb[i3 * 3 + 1];
        float nz = vb[i1 * 3 + 2] + vb[i2 * 3 + 2] + vb[i3 * 3 + 2];
        const float third = 1.0f / 3.0f;
        float* c = g_comb + (size_t)row * 6;
        c[0] = sx; c[1] = sy; c[2] = sz;
        c[3] = sx - nx * third;
        c[4] = sy - ny * third;
        c[5] = sz - nz * third;
    }
}

// ---------------------------------------------------------------------------
// Kernel 2: fused MLP: h = relu(c @ W1 + b1); h = LN(h)*g+b; out = h @ W2 + b2
// 64 rows per block, 256 threads. Full-fp32 GEMM via packed fma.rn.f32x2
// (2x FFMA throughput, no precision loss). h kept transposed in smem
// (stride 72 -> conflict-free), W2 double-buffered from L2.
// ---------------------------------------------------------------------------

#define MT 64
#define KC 8
#define HS_STRIDE 72
#define HS_F   (256 * HS_STRIDE)   // 18432 floats
#define W2B_F  (2 * KC * 256)      //  4096 floats
#define W1_F   (6 * 256)           //  1536 floats
#define SMEM_FLOATS (HS_F + W2B_F + W1_F + 3 * 256 + MT * 6)
#define SMEM_BYTES  (SMEM_FLOATS * 4)

__device__ __forceinline__ ull pk2(float lo, float hi) {
    ull r;
    asm("mov.b64 %0, {%1, %2};" : "=l"(r) : "f"(lo), "f"(hi));
    return r;
}
__device__ __forceinline__ void upk2(ull v, float &lo, float &hi) {
    asm("mov.b64 {%0, %1}, %2;" : "=f"(lo), "=f"(hi) : "l"(v));
}
__device__ __forceinline__ void ffma2(ull &d, ull a, ull b) {
    asm("fma.rn.f32x2 %0, %1, %2, %0;" : "+l"(d) : "l"(a), "l"(b));
}

__global__ void __launch_bounds__(256, 2) mlp_kernel(
    const float* __restrict__ W1, const float* __restrict__ b1,
    const float* __restrict__ gamma, const float* __restrict__ beta,
    const float* __restrict__ W2, const float* __restrict__ b2,
    float* __restrict__ out)
{
    extern __shared__ float sm[];
    float* hs  = sm;               // [256][HS_STRIDE], h transposed: hs[e][row]
    float* w2b = hs + HS_F;        // double buffer: 2 x [KC][256]
    float* w1s = w2b + W2B_F;      // [6][256]
    float* b1s = w1s + W1_F;
    float* gs  = b1s + 256;
    float* bs  = gs + 256;
    float* cmb = bs + 256;         // [MT][6]

    const int t = threadIdx.x;
    const int row0 = blockIdx.x * MT;

    for (int i = t; i < MT * 6; i += 256) cmb[i] = g_comb[(size_t)row0 * 6 + i];
    for (int i = t; i < W1_F; i += 256)   w1s[i] = W1[i];
    b1s[t] = b1[t]; gs[t] = gamma[t]; bs[t] = beta[t];
    __syncthreads();

    // ---- Phase A: h = relu(c @ W1 + b1), then LayerNorm, into transposed smem
    {
        const int r = t >> 2;      // row 0..63
        const int q = t & 3;       // col quadrant
        float c0 = cmb[r*6+0], c1 = cmb[r*6+1], c2 = cmb[r*6+2];
        float c3 = cmb[r*6+3], c4 = cmb[r*6+4], c5 = cmb[r*6+5];
        float sum = 0.f, sq = 0.f;
        #pragma unroll 8
        for (int jj = 0; jj < 64; jj++) {
            int e = q + 4 * jj;
            float x = b1s[e];
            x = fmaf(c0, w1s[e],        x);
            x = fmaf(c1, w1s[256 + e],  x);
            x = fmaf(c2, w1s[512 + e],  x);
            x = fmaf(c3, w1s[768 + e],  x);
            x = fmaf(c4, w1s[1024 + e], x);
            x = fmaf(c5, w1s[1280 + e], x);
            x = fmaxf(x, 0.f);
            hs[e * HS_STRIDE + r] = x;
            sum += x;
            sq = fmaf(x, x, sq);
        }
        sum += __shfl_xor_sync(FULLMASK, sum, 1);
        sq  += __shfl_xor_sync(FULLMASK, sq, 1);
        sum += __shfl_xor_sync(FULLMASK, sum, 2);
        sq  += __shfl_xor_sync(FULLMASK, sq, 2);
        float mu   = sum * (1.f / 256.f);
        float var  = sq * (1.f / 256.f) - mu * mu;
        float rstd = rsqrtf(var + 1e-5f);
        #pragma unroll 8
        for (int jj = 0; jj < 64; jj++) {
            int e = q + 4 * jj;
            float x = hs[e * HS_STRIDE + r];
            hs[e * HS_STRIDE + r] = (x - mu) * rstd * gs[e] + bs[e];
        }
    }
    __syncthreads();

    // ---- Phase B: out = h @ W2 + b2, 8x8 per thread with f32x2 pairs on rows
    const int lane = t & 31;
    const int wrp  = t >> 5;
    const int r0   = wrp * 8;

    ull acc[4][8];
    #pragma unroll
    for (int p = 0; p < 4; p++)
        #pragma unroll
        for (int j = 0; j < 8; j++) acc[p][j] = 0ull;

    const float4* wsrc = (const float4*)W2;
    // preload chunk 0
    {
        float4 f0 = wsrc[t];
        float4 f1 = wsrc[t + 256];
        float4* dst = (float4*)w2b;
        dst[t] = f0; dst[t + 256] = f1;
    }
    __syncthreads();

    #pragma unroll 1
    for (int c = 0; c < 32; c++) {
        float4 f0, f1;
        if (c < 31) {
            f0 = wsrc[(c + 1) * 512 + t];
            f1 = wsrc[(c + 1) * 512 + t + 256];
        }
        const float* wcur = w2b + (c & 1) * (KC * 256);
        #pragma unroll
        for (int kk = 0; kk < KC; kk++) {
            int k = c * KC + kk;
            const float* hp = hs + k * HS_STRIDE + r0;
            float4 ha = *(const float4*)hp;
            float4 hb = *(const float4*)(hp + 4);
            ull a0 = pk2(ha.x, ha.y);
            ull a1 = pk2(ha.z, ha.w);
            ull a2 = pk2(hb.x, hb.y);
            ull a3 = pk2(hb.z, hb.w);
            const float* wr = wcur + kk * 256 + lane;
            #pragma unroll
            for (int j = 0; j < 8; j++) {
                float w = wr[32 * j];
                ull wd = pk2(w, w);
                ffma2(acc[0][j], a0, wd);
                ffma2(acc[1][j], a1, wd);
                ffma2(acc[2][j], a2, wd);
                ffma2(acc[3][j], a3, wd);
            }
        }
        if (c < 31) {
            float4* dst = (float4*)(w2b + ((c + 1) & 1) * (KC * 256));
            dst[t] = f0; dst[t + 256] = f1;
        }
        __syncthreads();
    }

    // ---- Epilogue
    float bb[8];
    #pragma unroll
    for (int j = 0; j < 8; j++) bb[j] = b2[lane + 32 * j];
    #pragma unroll
    for (int p = 0; p < 4; p++) {
        float* o0 = out + (size_t)(row0 + r0 + 2 * p) * 256;
        float* o1 = o0 + 256;
        #pragma unroll
        for (int j = 0; j < 8; j++) {
            float lo, hi;
            upk2(acc[p][j], lo, hi);
            o0[lane + 32 * j] = lo + bb[j];
            o1[lane + 32 * j] = hi + bb[j];
        }
    }
}

// ---------------------------------------------------------------------------

extern "C" void kernel_launch(void* const* d_in, const int* in_sizes, int n_in,
                              void* d_out, int out_size) {
    const float* vel   = (const float*)d_in[0];
    const float* dm    = (const float*)d_in[1];
    const float* W1    = (const float*)d_in[2];
    const float* b1    = (const float*)d_in[3];
    const float* gamma = (const float*)d_in[4];
    const float* beta  = (const float*)d_in[5];
    const float* W2    = (const float*)d_in[6];
    const float* b2    = (const float*)d_in[7];
    float* out = (float*)d_out;

    topk_kernel<<<8192, 256>>>(dm, vel);

    cudaFuncSetAttribute(mlp_kernel, cudaFuncAttributeMaxDynamicSharedMemorySize,
                         SMEM_BYTES);
    mlp_kernel<<<1024, 256, SMEM_BYTES>>>(W1, b1, gamma, beta, W2, b2, out);
}

// round 5
// speedup vs baseline: 1.0045x; 1.0045x over previous
#include <cuda_runtime.h>
#include <cstdint>

typedef unsigned long long ull;
#define FULLMASK 0xFFFFFFFFu

// Scratch for combined features [vx,vy,vz, rx,ry,rz] per row (64*1024 rows).
__device__ float g_comb[64 * 1024 * 6];

// ---------------------------------------------------------------------------
// Kernel 1: top-4 smallest distances per row -> combined features
// One warp per row. Keys are ((u32)float_bits << 32) | index, so a single
// u64 '<' gives exact (value asc, index asc) ordering == JAX top_k ties.
// ---------------------------------------------------------------------------

__device__ __forceinline__ void cswap_u64(ull &a, ull &b) {
    if (b < a) { ull t = a; a = b; b = t; }
}

__device__ __forceinline__ void ins4(ull k, ull &k0, ull &k1, ull &k2, ull &k3) {
    if (k < k3) {
        k3 = k;
        cswap_u64(k2, k3);
        cswap_u64(k1, k2);
        cswap_u64(k0, k1);
    }
}

__global__ void __launch_bounds__(256) topk_kernel(const float* __restrict__ dm,
                                                   const float* __restrict__ vel) {
    const int warp = threadIdx.x >> 5;
    const int lane = threadIdx.x & 31;
    const int row  = blockIdx.x * 8 + warp;   // < 65536
    const float* drow = dm + (size_t)row * 1024;

    ull k0 = ~0ull, k1 = ~0ull, k2 = ~0ull, k3 = ~0ull;

    #pragma unroll 4
    for (int j = lane; j < 1024; j += 32) {
        float d = drow[j];
        ull key = ((ull)__float_as_uint(d) << 32) | (unsigned)j;
        ins4(key, k0, k1, k2, k3);
    }

    // Warp butterfly merge of per-lane sorted top-4 lists.
    #pragma unroll
    for (int off = 16; off; off >>= 1) {
        ull m0 = __shfl_xor_sync(FULLMASK, k0, off);
        ull m1 = __shfl_xor_sync(FULLMASK, k1, off);
        ull m2 = __shfl_xor_sync(FULLMASK, k2, off);
        ull m3 = __shfl_xor_sync(FULLMASK, k3, off);
        ins4(m0, k0, k1, k2, k3);
        ins4(m1, k0, k1, k2, k3);
        ins4(m2, k0, k1, k2, k3);
        ins4(m3, k0, k1, k2, k3);
    }

    if (lane == 0) {
        const int b = row >> 10;
        const int a = row & 1023;
        const float* vb = vel + (size_t)b * (1024 * 3);
        // ranks 1,2,3 (rank 0 dropped per idx[...,1:])
        const int i1 = (int)(unsigned)k1;
        const int i2 = (int)(unsigned)k2;
        const int i3 = (int)(unsigned)k3;
        float sx = vb[a * 3 + 0], sy = vb[a * 3 + 1], sz = vb[a * 3 + 2];
        float nx = vb[i1 * 3 + 0] + vb[i2 * 3 + 0] + vb[i3 * 3 + 0];
        float ny = vb[i1 * 3 + 1] + vb[i2 * 3 + 1] + vb[i3 * 3 + 1];
        float nz = vb[i1 * 3 + 2] + vb[i2 * 3 + 2] + vb[i3 * 3 + 2];
        const float third = 1.0f / 3.0f;
        float* c = g_comb + (size_t)row * 6;
        c[0] = sx; c[1] = sy; c[2] = sz;
        c[3] = sx - nx * third;
        c[4] = sy - ny * third;
        c[5] = sz - nz * third;
    }
}

// ---------------------------------------------------------------------------
// Kernel 2: fused MLP: h = relu(c @ W1 + b1); h = LN(h)*g+b; out = h @ W2 + b2
// 64 rows per block, 256 threads. Full-fp32 GEMM via packed fma.rn.f32x2
// (2x FFMA throughput, no precision loss). h kept transposed in smem
// (stride 72 -> conflict-free), W2 double-buffered from L2.
// ---------------------------------------------------------------------------

#define MT 64
#define KC 8
#define HS_STRIDE 72
#define HS_F   (256 * HS_STRIDE)   // 18432 floats
#define W2B_F  (2 * KC * 256)      //  4096 floats
#define W1_F   (6 * 256)           //  1536 floats
#define SMEM_FLOATS (HS_F + W2B_F + W1_F + 3 * 256 + MT * 6)
#define SMEM_BYTES  (SMEM_FLOATS * 4)

__device__ __forceinline__ ull pk2(float lo, float hi) {
    ull r;
    asm("mov.b64 %0, {%1, %2};" : "=l"(r) : "f"(lo), "f"(hi));
    return r;
}
__device__ __forceinline__ void upk2(ull v, float &lo, float &hi) {
    asm("mov.b64 {%0, %1}, %2;" : "=f"(lo), "=f"(hi) : "l"(v));
}
__device__ __forceinline__ void ffma2(ull &d, ull a, ull b) {
    asm("fma.rn.f32x2 %0, %1, %2, %0;" : "+l"(d) : "l"(a), "l"(b));
}

__global__ void __launch_bounds__(256, 2) mlp_kernel(
    const float* __restrict__ W1, const float* __restrict__ b1,
    const float* __restrict__ gamma, const float* __restrict__ beta,
    const float* __restrict__ W2, const float* __restrict__ b2,
    float* __restrict__ out)
{
    extern __shared__ float sm[];
    float* hs  = sm;               // [256][HS_STRIDE], h transposed: hs[e][row]
    float* w2b = hs + HS_F;        // double buffer: 2 x [KC][256]
    float* w1s = w2b + W2B_F;      // [6][256]
    float* b1s = w1s + W1_F;
    float* gs  = b1s + 256;
    float* bs  = gs + 256;
    float* cmb = bs + 256;         // [MT][6]

    const int t = threadIdx.x;
    const int row0 = blockIdx.x * MT;

    for (int i = t; i < MT * 6; i += 256) cmb[i] = g_comb[(size_t)row0 * 6 + i];
    for (int i = t; i < W1_F; i += 256)   w1s[i] = W1[i];
    b1s[t] = b1[t]; gs[t] = gamma[t]; bs[t] = beta[t];
    __syncthreads();

    // ---- Phase A: h = relu(c @ W1 + b1), then LayerNorm, into transposed smem
    {
        const int r = t >> 2;      // row 0..63
        const int q = t & 3;       // col quadrant
        float c0 = cmb[r*6+0], c1 = cmb[r*6+1], c2 = cmb[r*6+2];
        float c3 = cmb[r*6+3], c4 = cmb[r*6+4], c5 = cmb[r*6+5];
        float sum = 0.f, sq = 0.f;
        #pragma unroll 8
        for (int jj = 0; jj < 64; jj++) {
            int e = q + 4 * jj;
            float x = b1s[e];
            x = fmaf(c0, w1s[e],        x);
            x = fmaf(c1, w1s[256 + e],  x);
            x = fmaf(c2, w1s[512 + e],  x);
            x = fmaf(c3, w1s[768 + e],  x);
            x = fmaf(c4, w1s[1024 + e], x);
            x = fmaf(c5, w1s[1280 + e], x);
            x = fmaxf(x, 0.f);
            hs[e * HS_STRIDE + r] = x;
            sum += x;
            sq = fmaf(x, x, sq);
        }
        sum += __shfl_xor_sync(FULLMASK, sum, 1);
        sq  += __shfl_xor_sync(FULLMASK, sq, 1);
        sum += __shfl_xor_sync(FULLMASK, sum, 2);
        sq  += __shfl_xor_sync(FULLMASK, sq, 2);
        float mu   = sum * (1.f / 256.f);
        float var  = sq * (1.f / 256.f) - mu * mu;
        float rstd = rsqrtf(var + 1e-5f);
        #pragma unroll 8
        for (int jj = 0; jj < 64; jj++) {
            int e = q + 4 * jj;
            float x = hs[e * HS_STRIDE + r];
            hs[e * HS_STRIDE + r] = (x - mu) * rstd * gs[e] + bs[e];
        }
    }
    __syncthreads();

    // ---- Phase B: out = h @ W2 + b2, 8x8 per thread with f32x2 pairs on rows
    const int lane = t & 31;
    const int wrp  = t >> 5;
    const int r0   = wrp * 8;

    ull acc[4][8];
    #pragma unroll
    for (int p = 0; p < 4; p++)
        #pragma unroll
        for (int j = 0; j < 8; j++) acc[p][j] = 0ull;

    const float4* wsrc = (const float4*)W2;
    // preload chunk 0
    {
        float4 f0 = wsrc[t];
        float4 f1 = wsrc[t + 256];
        float4* dst = (float4*)w2b;
        dst[t] = f0; dst[t + 256] = f1;
    }
    __syncthreads();

    #pragma unroll 1
    for (int c = 0; c < 32; c++) {
        float4 f0, f1;
        if (c < 31) {
            f0 = wsrc[(c + 1) * 512 + t];
            f1 = wsrc[(c + 1) * 512 + t + 256];
        }
        const float* wcur = w2b + (c & 1) * (KC * 256);
        #pragma unroll
        for (int kk = 0; kk < KC; kk++) {
            int k = c * KC + kk;
            const float* hp = hs + k * HS_STRIDE + r0;
            float4 ha = *(const float4*)hp;
            float4 hb = *(const float4*)(hp + 4);
            ull a0 = pk2(ha.x, ha.y);
            ull a1 = pk2(ha.z, ha.w);
            ull a2 = pk2(hb.x, hb.y);
            ull a3 = pk2(hb.z, hb.w);
            const float* wr = wcur + kk * 256 + lane;
            #pragma unroll
            for (int j = 0; j < 8; j++) {
                float w = wr[32 * j];
                ull wd = pk2(w, w);
                ffma2(acc[0][j], a0, wd);
                ffma2(acc[1][j], a1, wd);
                ffma2(acc[2][j], a2, wd);
                ffma2(acc[3][j], a3, wd);
            }
        }
        if (c < 31) {
            float4* dst = (float4*)(w2b + ((c + 1) & 1) * (KC * 256));
            dst[t] = f0; dst[t + 256] = f1;
        }
        __syncthreads();
    }

    // ---- Epilogue
    float bb[8];
    #pragma unroll
    for (int j = 0; j < 8; j++) bb[j] = b2[lane + 32 * j];
    #pragma unroll
    for (int p = 0; p < 4; p++) {
        float* o0 = out + (size_t)(row0 + r0 + 2 * p) * 256;
        float* o1 = o0 + 256;
        #pragma unroll
        for (int j = 0; j < 8; j++) {
            float lo, hi;
            upk2(acc[p][j], lo, hi);
            o0[lane + 32 * j] = lo + bb[j];
            o1[lane + 32 * j] = hi + bb[j];
        }
    }
}

// ---------------------------------------------------------------------------

extern "C" void kernel_launch(void* const* d_in, const int* in_sizes, int n_in,
                              void* d_out, int out_size) {
    const float* vel   = (const float*)d_in[0];
    const float* dm    = (const float*)d_in[1];
    const float* W1    = (const float*)d_in[2];
    const float* b1    = (const float*)d_in[3];
    const float* gamma = (const float*)d_in[4];
    const float* beta  = (const float*)d_in[5];
    const float* W2    = (const float*)d_in[6];
    const float* b2    = (const float*)d_in[7];
    float* out = (float*)d_out;

    topk_kernel<<<8192, 256>>>(dm, vel);

    cudaFuncSetAttribute(mlp_kernel, cudaFuncAttributeMaxDynamicSharedMemorySize,
                         SMEM_BYTES);
    mlp_kernel<<<1024, 256, SMEM_BYTES>>>(W1, b1, gamma, beta, W2, b2, out);
}

// round 6
// speedup vs baseline: 1.0056x; 1.0011x over previous
#include <cuda_runtime.h>
#include <cstdint>

typedef unsigned long long ull;
#define FULLMASK 0xFFFFFFFFu

// Scratch for combined features [vx,vy,vz, rx,ry,rz] per row (64*1024 rows).
__device__ float g_comb[64 * 1024 * 6];

// ---------------------------------------------------------------------------
// Kernel 1: top-4 smallest distances per row -> combined features
// One warp per row. Keys are ((u32)float_bits << 32) | index, so a single
// u64 '<' gives exact (value asc, index asc) ordering == JAX top_k ties.
// ---------------------------------------------------------------------------

__device__ __forceinline__ void cswap_u64(ull &a, ull &b) {
    if (b < a) { ull t = a; a = b; b = t; }
}

__device__ __forceinline__ void ins4(ull k, ull &k0, ull &k1, ull &k2, ull &k3) {
    if (k < k3) {
        k3 = k;
        cswap_u64(k2, k3);
        cswap_u64(k1, k2);
        cswap_u64(k0, k1);
    }
}

__global__ void __launch_bounds__(256) topk_kernel(const float* __restrict__ dm,
                                                   const float* __restrict__ vel) {
    const int warp = threadIdx.x >> 5;
    const int lane = threadIdx.x & 31;
    const int row  = blockIdx.x * 8 + warp;   // < 65536
    const float* drow = dm + (size_t)row * 1024;

    ull k0 = ~0ull, k1 = ~0ull, k2 = ~0ull, k3 = ~0ull;

    #pragma unroll 4
    for (int j = lane; j < 1024; j += 32) {
        float d = drow[j];
        ull key = ((ull)__float_as_uint(d) << 32) | (unsigned)j;
        ins4(key, k0, k1, k2, k3);
    }

    // Warp butterfly merge of per-lane sorted top-4 lists.
    #pragma unroll
    for (int off = 16; off; off >>= 1) {
        ull m0 = __shfl_xor_sync(FULLMASK, k0, off);
        ull m1 = __shfl_xor_sync(FULLMASK, k1, off);
        ull m2 = __shfl_xor_sync(FULLMASK, k2, off);
        ull m3 = __shfl_xor_sync(FULLMASK, k3, off);
        ins4(m0, k0, k1, k2, k3);
        ins4(m1, k0, k1, k2, k3);
        ins4(m2, k0, k1, k2, k3);
        ins4(m3, k0, k1, k2, k3);
    }

    if (lane == 0) {
        const int b = row >> 10;
        const int a = row & 1023;
        const float* vb = vel + (size_t)b * (1024 * 3);
        // ranks 1,2,3 (rank 0 dropped per idx[...,1:])
        const int i1 = (int)(unsigned)k1;
        const int i2 = (int)(unsigned)k2;
        const int i3 = (int)(unsigned)k3;
        float sx = vb[a * 3 + 0], sy = vb[a * 3 + 1], sz = vb[a * 3 + 2];
        float nx = vb[i1 * 3 + 0] + vb[i2 * 3 + 0] + vb[i3 * 3 + 0];
        float ny = vb[i1 * 3 + 1] + vb[i2 * 3 + 1] + vb[i3 * 3 + 1];
        float nz = vb[i1 * 3 + 2] + vb[i2 * 3 + 2] + vb[i3 * 3 + 2];
        const float third = 1.0f / 3.0f;
        float* c = g_comb + (size_t)row * 6;
        c[0] = sx; c[1] = sy; c[2] = sz;
        c[3] = sx - nx * third;
        c[4] = sy - ny * third;
        c[5] = sz - nz * third;
    }
}

// ---------------------------------------------------------------------------
// Kernel 2: fused MLP: h = relu(c @ W1 + b1); h = LN(h)*g+b; out = h @ W2 + b2
// 64 rows per block, 256 threads. Full-fp32 GEMM via packed fma.rn.f32x2
// (2x FFMA throughput, no precision loss). h kept transposed in smem
// (stride 72 -> conflict-free), W2 double-buffered from L2.
// ---------------------------------------------------------------------------

#define MT 64
#define KC 8
#define HS_STRIDE 72
#define HS_F   (256 * HS_STRIDE)   // 18432 floats
#define W2B_F  (2 * KC * 256)      //  4096 floats
#define W1_F   (6 * 256)           //  1536 floats
#define SMEM_FLOATS (HS_F + W2B_F + W1_F + 3 * 256 + MT * 6)
#define SMEM_BYTES  (SMEM_FLOATS * 4)

__device__ __forceinline__ ull pk2(float lo, float hi) {
    ull r;
    asm("mov.b64 %0, {%1, %2};" : "=l"(r) : "f"(lo), "f"(hi));
    return r;
}
__device__ __forceinline__ void upk2(ull v, float &lo, float &hi) {
    asm("mov.b64 {%0, %1}, %2;" : "=f"(lo), "=f"(hi) : "l"(v));
}
__device__ __forceinline__ void ffma2(ull &d, ull a, ull b) {
    asm("fma.rn.f32x2 %0, %1, %2, %0;" : "+l"(d) : "l"(a), "l"(b));
}

__global__ void __launch_bounds__(256, 2) mlp_kernel(
    const float* __restrict__ W1, const float* __restrict__ b1,
    const float* __restrict__ gamma, const float* __restrict__ beta,
    const float* __restrict__ W2, const float* __restrict__ b2,
    float* __restrict__ out)
{
    extern __shared__ float sm[];
    float* hs  = sm;               // [256][HS_STRIDE], h transposed: hs[e][row]
    float* w2b = hs + HS_F;        // double buffer: 2 x [KC][256]
    float* w1s = w2b + W2B_F;      // [6][256]
    float* b1s = w1s + W1_F;
    float* gs  = b1s + 256;
    float* bs  = gs + 256;
    float* cmb = bs + 256;         // [MT][6]

    const int t = threadIdx.x;
    const int row0 = blockIdx.x * MT;

    for (int i = t; i < MT * 6; i += 256) cmb[i] = g_comb[(size_t)row0 * 6 + i];
    for (int i = t; i < W1_F; i += 256)   w1s[i] = W1[i];
    b1s[t] = b1[t]; gs[t] = gamma[t]; bs[t] = beta[t];
    __syncthreads();

    // ---- Phase A: h = relu(c @ W1 + b1), then LayerNorm, into transposed smem
    {
        const int r = t >> 2;      // row 0..63
        const int q = t & 3;       // col quadrant
        float c0 = cmb[r*6+0], c1 = cmb[r*6+1], c2 = cmb[r*6+2];
        float c3 = cmb[r*6+3], c4 = cmb[r*6+4], c5 = cmb[r*6+5];
        float sum = 0.f, sq = 0.f;
        #pragma unroll 8
        for (int jj = 0; jj < 64; jj++) {
            int e = q + 4 * jj;
            float x = b1s[e];
            x = fmaf(c0, w1s[e],        x);
            x = fmaf(c1, w1s[256 + e],  x);
            x = fmaf(c2, w1s[512 + e],  x);
            x = fmaf(c3, w1s[768 + e],  x);
            x = fmaf(c4, w1s[1024 + e], x);
            x = fmaf(c5, w1s[1280 + e], x);
            x = fmaxf(x, 0.f);
            hs[e * HS_STRIDE + r] = x;
            sum += x;
            sq = fmaf(x, x, sq);
        }
        sum += __shfl_xor_sync(FULLMASK, sum, 1);
        sq  += __shfl_xor_sync(FULLMASK, sq, 1);
        sum += __shfl_xor_sync(FULLMASK, sum, 2);
        sq  += __shfl_xor_sync(FULLMASK, sq, 2);
        float mu   = sum * (1.f / 256.f);
        float var  = sq * (1.f / 256.f) - mu * mu;
        float rstd = rsqrtf(var + 1e-5f);
        #pragma unroll 8
        for (int jj = 0; jj < 64; jj++) {
            int e = q + 4 * jj;
            float x = hs[e * HS_STRIDE + r];
            hs[e * HS_STRIDE + r] = (x - mu) * rstd * gs[e] + bs[e];
        }
    }
    __syncthreads();

    // ---- Phase B: out = h @ W2 + b2, 8x8 per thread with f32x2 pairs on rows
    const int lane = t & 31;
    const int wrp  = t >> 5;
    const int r0   = wrp * 8;

    ull acc[4][8];
    #pragma unroll
    for (int p = 0; p < 4; p++)
        #pragma unroll
        for (int j = 0; j < 8; j++) acc[p][j] = 0ull;

    const float4* wsrc = (const float4*)W2;
    // preload chunk 0
    {
        float4 f0 = wsrc[t];
        float4 f1 = wsrc[t + 256];
        float4* dst = (float4*)w2b;
        dst[t] = f0; dst[t + 256] = f1;
    }
    __syncthreads();

    #pragma unroll 1
    for (int c = 0; c < 32; c++) {
        float4 f0, f1;
        if (c < 31) {
            f0 = wsrc[(c + 1) * 512 + t];
            f1 = wsrc[(c + 1) * 512 + t + 256];
        }
        const float* wcur = w2b + (c & 1) * (KC * 256);
        #pragma unroll
        for (int kk = 0; kk < KC; kk++) {
            int k = c * KC + kk;
            const float* hp = hs + k * HS_STRIDE + r0;
            float4 ha = *(const float4*)hp;
            float4 hb = *(const float4*)(hp + 4);
            ull a0 = pk2(ha.x, ha.y);
            ull a1 = pk2(ha.z, ha.w);
            ull a2 = pk2(hb.x, hb.y);
            ull a3 = pk2(hb.z, hb.w);
            const float* wr = wcur + kk * 256 + lane;
            #pragma unroll
            for (int j = 0; j < 8; j++) {
                float w = wr[32 * j];
                ull wd = pk2(w, w);
                ffma2(acc[0][j], a0, wd);
                ffma2(acc[1][j], a1, wd);
                ffma2(acc[2][j], a2, wd);
                ffma2(acc[3][j], a3, wd);
            }
        }
        if (c < 31) {
            float4* dst = (float4*)(w2b + ((c + 1) & 1) * (KC * 256));
            dst[t] = f0; dst[t + 256] = f1;
        }
        __syncthreads();
    }

    // ---- Epilogue
    float bb[8];
    #pragma unroll
    for (int j = 0; j < 8; j++) bb[j] = b2[lane + 32 * j];
    #pragma unroll
    for (int p = 0; p < 4; p++) {
        float* o0 = out + (size_t)(row0 + r0 + 2 * p) * 256;
        float* o1 = o0 + 256;
        #pragma unroll
        for (int j = 0; j < 8; j++) {
            float lo, hi;
            upk2(acc[p][j], lo, hi);
            o0[lane + 32 * j] = lo + bb[j];
            o1[lane + 32 * j] = hi + bb[j];
        }
    }
}

// ---------------------------------------------------------------------------

extern "C" void kernel_launch(void* const* d_in, const int* in_sizes, int n_in,
                              void* d_out, int out_size) {
    const float* vel   = (const float*)d_in[0];
    const float* dm    = (const float*)d_in[1];
    const float* W1    = (const float*)d_in[2];
    const float* b1    = (const float*)d_in[3];
    const float* gamma = (const float*)d_in[4];
    const float* beta  = (const float*)d_in[5];
    const float* W2    = (const float*)d_in[6];
    const float* b2    = (const float*)d_in[7];
    float* out = (float*)d_out;

    topk_kernel<<<8192, 256>>>(dm, vel);

    cudaFuncSetAttribute(mlp_kernel, cudaFuncAttributeMaxDynamicSharedMemorySize,
                         SMEM_BYTES);
    mlp_kernel<<<1024, 256, SMEM_BYTES>>>(W1, b1, gamma, beta, W2, b2, out);
}